// round 12
// baseline (speedup 1.0000x reference)
#include <cuda_runtime.h>

#define Dd    64
#define HALF  512
#define NT    512
#define PB    544             // parts buffer stride: 4 halves x 2 batches x 68

typedef unsigned long long u64;

__device__ float g_vL[64 * Dd];
__device__ float g_wR[64 * Dd];
__device__ float g_Wt[HALF * 64 * 128];   // transposed W_right, 16MB scratch

__device__ __forceinline__ u64 pk2(float a, float b) {
    u64 r; asm("mov.b64 %0, {%1,%2};" : "=l"(r) : "f"(a), "f"(b)); return r;
}
__device__ __forceinline__ u64 fma2(u64 a, u64 b, u64 c) {
    u64 d; asm("fma.rn.f32x2 %0, %1, %2, %3;" : "=l"(d) : "l"(a), "l"(b), "l"(c)); return d;
}
__device__ __forceinline__ float2 up2(u64 v) {
    float2 f; asm("mov.b64 {%0,%1}, %2;" : "=f"(f.x), "=f"(f.y) : "l"(v)); return f;
}

// g_Wt[s][r][2l+i] = Wr[s][l][2r+i]
__global__ void __launch_bounds__(256, 4)
transpose_kernel(const float* __restrict__ Wr)
{
    __shared__ float tile[64 * 132];
    const int s = blockIdx.x;
    const float* in = Wr + (size_t)s * 8192;
    float* out = g_Wt + (size_t)s * 8192;
    for (int idx = threadIdx.x; idx < 8192; idx += 256)
        tile[(idx >> 7) * 132 + (idx & 127)] = in[idx];
    __syncthreads();
    for (int idx = threadIdx.x; idx < 8192; idx += 256) {
        int r = idx >> 7, c = idx & 127;
        out[idx] = tile[(c >> 1) * 132 + 2 * r + (c & 1)];
    }
}

// 16 warps: w = qh*4+rh (qh: q-quarter, rh: c-quarter); lane = rr*8+qs.
// Thread: contraction rows crow0..crow0+3 (contiguous), outputs q0,q0+1, 2 batches.
// parts[buf][rh'][b][68] quarter-partials; consumers sum 4. One barrier/step.
__global__ void __launch_bounds__(NT, 1)
chain_kernel(const float* __restrict__ x, const float* __restrict__ Wl)
{
    __shared__ float xs[2 * 1024];
    __shared__ float parts[2 * PB];

    const int t     = threadIdx.x;
    const int side  = blockIdx.x >> 5;         // 32 CTAs per side
    const int gb    = (blockIdx.x & 31) * 2;
    const int w     = t >> 5, lane = t & 31;
    const int qh    = w >> 2, rh = w & 3;
    const int rr    = lane >> 3, qs = lane & 7;
    const int q0    = qh * 16 + qs * 2;
    const int crow0 = rh * 16 + rr * 4;

    for (int i = t; i < 2048; i += NT) {
        int b2 = i >> 10;
        xs[i] = x[(gb + b2) * 2048 + side * 1024 + (i & 1023)];
    }
    for (int i = t; i < 2 * PB; i += NT) parts[i] = 0.f;
    __syncthreads();
    if (t < 2) parts[t * 68] = 1.f;            // buf0, rh'=0: v = e0 per batch
    __syncthreads();

    const float* Wbase = side ? (g_Wt + (size_t)(HALF - 1) * 8192) : Wl;
    const long   strd  = side ? -8192 : 8192;
    const float* Wp    = Wbase + crow0 * 128 + qh * 32 + qs * 4;

    ulonglong2 wA[4], wB[4];

#define PRE(i, wreg)                                                          \
    if ((i) < HALF) {                                                         \
        const float* _p = Wp + (long)(i) * strd;                              \
        _Pragma("unroll")                                                     \
        for (int g = 0; g < 4; g++)                                           \
            wreg[g] = *(const ulonglong2*)(_p + g * 128);                     \
    }

#define STEP(i, wreg) {                                                       \
    const int sl = side ? (HALF - 1 - (i)) : (i);                             \
    const float* pin  = parts + ((i) & 1) * PB;                               \
    float*       pout = parts + (((i) + 1) & 1) * PB;                         \
    float4 s00 = *(const float4*)(pin +   0 + crow0);                         \
    float4 s01 = *(const float4*)(pin + 136 + crow0);                         \
    float4 s02 = *(const float4*)(pin + 272 + crow0);                         \
    float4 s03 = *(const float4*)(pin + 408 + crow0);                         \
    float4 s10 = *(const float4*)(pin +  68 + crow0);                         \
    float4 s11 = *(const float4*)(pin + 204 + crow0);                         \
    float4 s12 = *(const float4*)(pin + 340 + crow0);                         \
    float4 s13 = *(const float4*)(pin + 476 + crow0);                         \
    float vs0[4], vs1[4];                                                     \
    vs0[0] = (s00.x + s01.x) + (s02.x + s03.x);                               \
    vs0[1] = (s00.y + s01.y) + (s02.y + s03.y);                               \
    vs0[2] = (s00.z + s01.z) + (s02.z + s03.z);                               \
    vs0[3] = (s00.w + s01.w) + (s02.w + s03.w);                               \
    vs1[0] = (s10.x + s11.x) + (s12.x + s13.x);                               \
    vs1[1] = (s10.y + s11.y) + (s12.y + s13.y);                               \
    vs1[2] = (s10.z + s11.z) + (s12.z + s13.z);                               \
    vs1[3] = (s10.w + s11.w) + (s12.w + s13.w);                               \
    u64 acc00 = 0ull, acc01 = 0ull, acc10 = 0ull, acc11 = 0ull;               \
    _Pragma("unroll")                                                         \
    for (int g = 0; g < 4; g++) {                                             \
        u64 wx = wreg[g].x, wy = wreg[g].y;                                   \
        u64 v0 = pk2(vs0[g], vs0[g]);                                         \
        u64 v1 = pk2(vs1[g], vs1[g]);                                         \
        acc00 = fma2(v0, wx, acc00); acc01 = fma2(v0, wy, acc01);             \
        acc10 = fma2(v1, wx, acc10); acc11 = fma2(v1, wy, acc11);             \
    }                                                                         \
    float2 xv0 = *(const float2*)(xs + sl * 2);                               \
    float2 xv1 = *(const float2*)(xs + 1024 + sl * 2);                        \
    float2 A;                                                                 \
    A = up2(acc00); float p00 = xv0.x * A.x + xv0.y * A.y;                    \
    A = up2(acc01); float p01 = xv0.x * A.x + xv0.y * A.y;                    \
    A = up2(acc10); float p10 = xv1.x * A.x + xv1.y * A.y;                    \
    A = up2(acc11); float p11 = xv1.x * A.x + xv1.y * A.y;                    \
    p00 += __shfl_xor_sync(~0u, p00, 8);  p00 += __shfl_xor_sync(~0u, p00, 16);\
    p01 += __shfl_xor_sync(~0u, p01, 8);  p01 += __shfl_xor_sync(~0u, p01, 16);\
    p10 += __shfl_xor_sync(~0u, p10, 8);  p10 += __shfl_xor_sync(~0u, p10, 16);\
    p11 += __shfl_xor_sync(~0u, p11, 8);  p11 += __shfl_xor_sync(~0u, p11, 16);\
    if (rr == 0) {                                                            \
        *(float2*)(pout + rh * 136 + q0)      = make_float2(p00, p01);        \
        *(float2*)(pout + rh * 136 + 68 + q0) = make_float2(p10, p11);        \
    }                                                                         \
    __syncthreads();                                                          \
}

    PRE(0, wA);
    for (int i = 0; i < HALF; i += 2) {
        PRE(i + 1, wB);
        STEP(i, wA);
        PRE(i + 2, wA);
        STEP(i + 1, wB);
    }

    // final v in buffer 0: sum the 4 quarter-partials
    if (t < 128) {
        int b = t >> 6, q = t & 63;
        float vfin = (parts[b * 68 + q]       + parts[136 + b * 68 + q])
                   + (parts[272 + b * 68 + q] + parts[408 + b * 68 + q]);
        (side ? g_wR : g_vL)[(gb + b) * Dd + q] = vfin;
    }
#undef PRE
#undef STEP
}

// out[b,o] = sum_{l,r} vL[b,l] * core[o,l,r] * wR[b,r]
__global__ void __launch_bounds__(320, 4)
combine_kernel(const float* __restrict__ core, float* __restrict__ out)
{
    __shared__ float vsh[Dd], wsh[Dd];
    const int b    = blockIdx.x;
    const int t    = threadIdx.x;
    const int o    = t >> 5;
    const int lane = t & 31;

    if (t < Dd) { vsh[t] = g_vL[b * Dd + t]; wsh[t] = g_wR[b * Dd + t]; }
    __syncthreads();

    const float* co = core + o * (Dd * Dd);
    float a0 = 0.f, a1 = 0.f;
#pragma unroll 8
    for (int l = 0; l < Dd; ++l) {
        float vl = vsh[l];
        a0 = fmaf(vl, co[l * Dd + lane],      a0);
        a1 = fmaf(vl, co[l * Dd + lane + 32], a1);
    }
    float p = a0 * wsh[lane] + a1 * wsh[lane + 32];
#pragma unroll
    for (int off = 16; off; off >>= 1)
        p += __shfl_down_sync(0xffffffffu, p, off);
    if (lane == 0) out[b * 10 + o] = p;
}

extern "C" void kernel_launch(void* const* d_in, const int* in_sizes, int n_in,
                              void* d_out, int out_size)
{
    const float* x    = (const float*)d_in[0];
    const float* Wl   = (const float*)d_in[1];
    const float* core = (const float*)d_in[2];
    const float* Wr   = (const float*)d_in[3];
    float* out = (float*)d_out;

    transpose_kernel<<<HALF, 256>>>(Wr);
    chain_kernel<<<64, NT>>>(x, Wl);
    combine_kernel<<<64, 320>>>(core, out);
}

// round 13
// speedup vs baseline: 2.0175x; 2.0175x over previous
#include <cuda_runtime.h>

#define Dd    64
#define HALF  512
#define NT    256

typedef unsigned long long u64;

__device__ float g_vL[64 * Dd];
__device__ float g_wR[64 * Dd];
__device__ float g_Wt[HALF * 64 * 128];   // transposed W_right, 16MB scratch

__device__ __forceinline__ u64 pk2(float a, float b) {
    u64 r; asm("mov.b64 %0, {%1,%2};" : "=l"(r) : "f"(a), "f"(b)); return r;
}
__device__ __forceinline__ u64 fma2(u64 a, u64 b, u64 c) {
    u64 d; asm("fma.rn.f32x2 %0, %1, %2, %3;" : "=l"(d) : "l"(a), "l"(b), "l"(c)); return d;
}
__device__ __forceinline__ float2 up2(u64 v) {
    float2 f; asm("mov.b64 {%0,%1}, %2;" : "=f"(f.x), "=f"(f.y) : "l"(v)); return f;
}

// g_Wt[s][r][2l+i] = Wr[s][l][2r+i]
__global__ void __launch_bounds__(256, 4)
transpose_kernel(const float* __restrict__ Wr)
{
    __shared__ float tile[64 * 132];
    const int s = blockIdx.x;
    const float* in = Wr + (size_t)s * 8192;
    float* out = g_Wt + (size_t)s * 8192;
    for (int idx = threadIdx.x; idx < 8192; idx += 256)
        tile[(idx >> 7) * 132 + (idx & 127)] = in[idx];
    __syncthreads();
    for (int idx = threadIdx.x; idx < 8192; idx += 256) {
        int r = idx >> 7, c = idx & 127;
        out[idx] = tile[(c >> 1) * 132 + 2 * r + (c & 1)];
    }
}

// R11 structure, prefetch distance 2 (triple W register buffer).
// warp w = qh*2+rh (qh: q-quarter, rh: c-half); lane = rr*8+qs.
// Thread: rows crow0..crow0+8 (contiguous), q outputs q0,q0+1, both batches.
// parts[buf][rh'][b][68] half-partials; consumers sum 2. One barrier/step.
__global__ void __launch_bounds__(NT, 1)
chain_kernel(const float* __restrict__ x, const float* __restrict__ Wl)
{
    __shared__ float xs[2 * 1024];
    __shared__ float parts[2 * 272];

    const int t     = threadIdx.x;
    const int side  = blockIdx.x >> 5;         // 32 CTAs per side
    const int gb    = (blockIdx.x & 31) * 2;
    const int w     = t >> 5, lane = t & 31;
    const int qh    = w >> 1, rh = w & 1;
    const int rr    = lane >> 3, qs = lane & 7;
    const int q0    = qh * 16 + qs * 2;
    const int crow0 = rh * 32 + rr * 8;

    for (int i = t; i < 2048; i += NT) {
        int b2 = i >> 10;
        xs[i] = x[(gb + b2) * 2048 + side * 1024 + (i & 1023)];
    }
    for (int i = t; i < 2 * 272; i += NT) parts[i] = 0.f;
    __syncthreads();
    if (t < 2) parts[t * 68] = 1.f;            // buf0, rh'=0: v = e0 per batch
    __syncthreads();

    const float* Wbase = side ? (g_Wt + (size_t)(HALF - 1) * 8192) : Wl;
    const long   strd  = side ? -8192 : 8192;
    const float* Wp    = Wbase + crow0 * 128 + qh * 32 + qs * 4;

    ulonglong2 wA[8], wB[8], wC[8];

#define PRE(i, wreg)                                                          \
    if ((i) < HALF) {                                                         \
        const float* _p = Wp + (long)(i) * strd;                              \
        _Pragma("unroll")                                                     \
        for (int g = 0; g < 8; g++)                                           \
            wreg[g] = *(const ulonglong2*)(_p + g * 128);                     \
    }

#define STEP(i, wreg) {                                                       \
    const int sl = side ? (HALF - 1 - (i)) : (i);                             \
    const float* pin  = parts + ((i) & 1) * 272;                              \
    float*       pout = parts + (((i) + 1) & 1) * 272;                        \
    float4 a0 = *(const float4*)(pin + crow0);                                \
    float4 a1 = *(const float4*)(pin + crow0 + 4);                            \
    float4 b0 = *(const float4*)(pin + 136 + crow0);                          \
    float4 b1 = *(const float4*)(pin + 136 + crow0 + 4);                      \
    float4 c0 = *(const float4*)(pin + 68 + crow0);                           \
    float4 c1 = *(const float4*)(pin + 68 + crow0 + 4);                       \
    float4 d0 = *(const float4*)(pin + 204 + crow0);                          \
    float4 d1 = *(const float4*)(pin + 204 + crow0 + 4);                      \
    float vs0[8], vs1[8];                                                     \
    vs0[0]=a0.x+b0.x; vs0[1]=a0.y+b0.y; vs0[2]=a0.z+b0.z; vs0[3]=a0.w+b0.w;   \
    vs0[4]=a1.x+b1.x; vs0[5]=a1.y+b1.y; vs0[6]=a1.z+b1.z; vs0[7]=a1.w+b1.w;   \
    vs1[0]=c0.x+d0.x; vs1[1]=c0.y+d0.y; vs1[2]=c0.z+d0.z; vs1[3]=c0.w+d0.w;   \
    vs1[4]=c1.x+d1.x; vs1[5]=c1.y+d1.y; vs1[6]=c1.z+d1.z; vs1[7]=c1.w+d1.w;   \
    u64 acc00 = 0ull, acc01 = 0ull, acc10 = 0ull, acc11 = 0ull;               \
    _Pragma("unroll")                                                         \
    for (int g = 0; g < 8; g++) {                                             \
        u64 wx = wreg[g].x, wy = wreg[g].y;                                   \
        u64 v0 = pk2(vs0[g], vs0[g]);                                         \
        u64 v1 = pk2(vs1[g], vs1[g]);                                         \
        acc00 = fma2(v0, wx, acc00); acc01 = fma2(v0, wy, acc01);             \
        acc10 = fma2(v1, wx, acc10); acc11 = fma2(v1, wy, acc11);             \
    }                                                                         \
    float2 xv0 = *(const float2*)(xs + sl * 2);                               \
    float2 xv1 = *(const float2*)(xs + 1024 + sl * 2);                        \
    float2 A;                                                                 \
    A = up2(acc00); float p00 = xv0.x * A.x + xv0.y * A.y;                    \
    A = up2(acc01); float p01 = xv0.x * A.x + xv0.y * A.y;                    \
    A = up2(acc10); float p10 = xv1.x * A.x + xv1.y * A.y;                    \
    A = up2(acc11); float p11 = xv1.x * A.x + xv1.y * A.y;                    \
    p00 += __shfl_xor_sync(~0u, p00, 8);  p00 += __shfl_xor_sync(~0u, p00, 16);\
    p01 += __shfl_xor_sync(~0u, p01, 8);  p01 += __shfl_xor_sync(~0u, p01, 16);\
    p10 += __shfl_xor_sync(~0u, p10, 8);  p10 += __shfl_xor_sync(~0u, p10, 16);\
    p11 += __shfl_xor_sync(~0u, p11, 8);  p11 += __shfl_xor_sync(~0u, p11, 16);\
    if (rr == 0) {                                                            \
        *(float2*)(pout + rh * 136 + q0)      = make_float2(p00, p01);        \
        *(float2*)(pout + rh * 136 + 68 + q0) = make_float2(p10, p11);        \
    }                                                                         \
    __syncthreads();                                                          \
}

    // prefetch distance 2: entering each body iteration, A=W[i], B=W[i+1]
    PRE(0, wA);
    PRE(1, wB);
    for (int i = 0; i < 510; i += 3) {
        PRE(i + 2, wC);
        STEP(i, wA);
        PRE(i + 3, wA);
        STEP(i + 1, wB);
        PRE(i + 4, wB);
        STEP(i + 2, wC);
    }
    STEP(510, wA);
    STEP(511, wB);

    // final v in buffer (HALF & 1) == 0: sum the two rh partials
    if (t < 128) {
        int b = t >> 6, q = t & 63;
        float vfin = parts[b * 68 + q] + parts[136 + b * 68 + q];
        (side ? g_wR : g_vL)[(gb + b) * Dd + q] = vfin;
    }
#undef PRE
#undef STEP
}

// out[b,o] = sum_{l,r} vL[b,l] * core[o,l,r] * wR[b,r]
__global__ void __launch_bounds__(320, 4)
combine_kernel(const float* __restrict__ core, float* __restrict__ out)
{
    __shared__ float vsh[Dd], wsh[Dd];
    const int b    = blockIdx.x;
    const int t    = threadIdx.x;
    const int o    = t >> 5;
    const int lane = t & 31;

    if (t < Dd) { vsh[t] = g_vL[b * Dd + t]; wsh[t] = g_wR[b * Dd + t]; }
    __syncthreads();

    const float* co = core + o * (Dd * Dd);
    float a0 = 0.f, a1 = 0.f;
#pragma unroll 8
    for (int l = 0; l < Dd; ++l) {
        float vl = vsh[l];
        a0 = fmaf(vl, co[l * Dd + lane],      a0);
        a1 = fmaf(vl, co[l * Dd + lane + 32], a1);
    }
    float p = a0 * wsh[lane] + a1 * wsh[lane + 32];
#pragma unroll
    for (int off = 16; off; off >>= 1)
        p += __shfl_down_sync(0xffffffffu, p, off);
    if (lane == 0) out[b * 10 + o] = p;
}

extern "C" void kernel_launch(void* const* d_in, const int* in_sizes, int n_in,
                              void* d_out, int out_size)
{
    const float* x    = (const float*)d_in[0];
    const float* Wl   = (const float*)d_in[1];
    const float* core = (const float*)d_in[2];
    const float* Wr   = (const float*)d_in[3];
    float* out = (float*)d_out;

    transpose_kernel<<<HALF, 256>>>(Wr);
    chain_kernel<<<64, NT>>>(x, Wl);
    combine_kernel<<<64, 320>>>(core, out);
}